// round 2
// baseline (speedup 1.0000x reference)
#include <cuda_runtime.h>
#include <cstdint>

#define BB   8
#define SS   4096
#define HIDD 1024
#define HH   16
#define DHH  64

#define K1_CHUNKS   64               // chunks per batch
#define ROWS_PER    64               // rows per block (S / K1_CHUNKS)
#define K1_BLOCKS   (BB * K1_CHUNKS) // 512

// ---------- static scratch (no allocations allowed) ----------
__device__ float g_scratch[(size_t)K1_BLOCKS * HH * HIDD]; // 32 MB  per-block g partials
__device__ float hbar_scratch[(size_t)K1_BLOCKS * HIDD];   // 2 MB   per-block hbar partials
__device__ float wqk_eff[2 * HH * HIDD];                   // 128 KB effective q/k weights
__device__ float qs_buf[(size_t)BB * SS * HH];             // 2 MB   q_scores [b][s][h]
__device__ float hbar_final[BB * HIDD];
__device__ float kv_buf[BB * HH * DHH];
__device__ float mv_buf[BB * HH * DHH];
__device__ float invlen_buf[BB];

typedef unsigned long long u64;

__device__ __forceinline__ u64 ffma2(u64 a, u64 b, u64 c) {
    u64 d;
    asm("fma.rn.f32x2 %0, %1, %2, %3;" : "=l"(d) : "l"(a), "l"(b), "l"(c));
    return d;
}
__device__ __forceinline__ u64 pack2(float x, float y) {
    u64 r; asm("mov.b64 %0, {%1,%2};" : "=l"(r) : "f"(x), "f"(y)); return r;
}
__device__ __forceinline__ float2 unpack2(u64 v) {
    float2 r; asm("mov.b64 {%0,%1}, %2;" : "=f"(r.x), "=f"(r.y) : "l"(v)); return r;
}

// ============================================================
// K0: wqk_eff[ch][h][e] = sum_d aw[h][d] * W[(h*64+d)][e]
// grid 32 (ch*16+h), block 256
// ============================================================
__global__ void k0_weff(const float* __restrict__ Wq,
                        const float* __restrict__ Wk,
                        const float* __restrict__ aw) {
    int ch = blockIdx.x >> 4, h = blockIdx.x & 15;
    const float* W = ch ? Wk : Wq;
    __shared__ float a_sh[DHH];
    if (threadIdx.x < DHH) a_sh[threadIdx.x] = aw[h * DHH + threadIdx.x];
    __syncthreads();
    for (int e = threadIdx.x; e < HIDD; e += blockDim.x) {
        float acc = 0.f;
#pragma unroll 8
        for (int d = 0; d < DHH; d++)
            acc += a_sh[d] * W[(size_t)(h * DHH + d) * HIDD + e];
        wqk_eff[(ch * HH + h) * HIDD + e] = acc;
    }
}

// ============================================================
// K1: TWO-PASS over 64 rows per block. Pass 1: q/k dots with weights
// register-resident (weights die at end of pass 1). Pass 2: re-read rows
// from L2 and accumulate g + hbar with g register-resident.
// Register liveness never exceeds ~190 -> no spills.
// grid 512, block 256 (8 warps; warp w owns heads 2w, 2w+1)
// ============================================================
__global__ void __launch_bounds__(256, 1)
k1_main(const float* __restrict__ hidden, const float* __restrict__ mask) {
    int blk = blockIdx.x;
    int b = blk / K1_CHUNKS;
    int chunk = blk % K1_CHUNKS;
    int s0 = chunk * ROWS_PER;
    int w = threadIdx.x >> 5, l = threadIdx.x & 31;
    int h0 = 2 * w;

    __shared__ float2 ks_sh[ROWS_PER * 8];  // [r][w] -> (ks_h0, ks_h1)
    __shared__ float  msk_sh[ROWS_PER];

    const float* rowbase = hidden + ((size_t)b * SS + s0) * HIDD;

    // -------------------- PASS 1: q/k dot products --------------------
    {
        u64 wq0[16], wq1[16], wk0[16], wk1[16];
        {
            const ulonglong2* pq0 = (const ulonglong2*)(wqk_eff + (0 * HH + h0) * HIDD) + l * 8;
            const ulonglong2* pq1 = (const ulonglong2*)(wqk_eff + (0 * HH + h0 + 1) * HIDD) + l * 8;
            const ulonglong2* pk0 = (const ulonglong2*)(wqk_eff + (1 * HH + h0) * HIDD) + l * 8;
            const ulonglong2* pk1 = (const ulonglong2*)(wqk_eff + (1 * HH + h0 + 1) * HIDD) + l * 8;
#pragma unroll
            for (int i = 0; i < 8; i++) {
                ulonglong2 t;
                t = pq0[i]; wq0[2 * i] = t.x; wq0[2 * i + 1] = t.y;
                t = pq1[i]; wq1[2 * i] = t.x; wq1[2 * i + 1] = t.y;
                t = pk0[i]; wk0[2 * i] = t.x; wk0[2 * i + 1] = t.y;
                t = pk1[i]; wk1[2 * i] = t.x; wk1[2 * i + 1] = t.y;
            }
        }

#pragma unroll 1
        for (int r = 0; r < ROWS_PER; r++) {
            const float* row = rowbase + (size_t)r * HIDD;
            if (r + 2 < ROWS_PER) {
                const char* pf = (const char*)(row + 2 * HIDD) + l * 128;
                asm volatile("prefetch.global.L2 [%0];" :: "l"(pf));
            }
            const ulonglong2* rp = (const ulonglong2*)row + l * 8;
            ulonglong2 rv[8];
#pragma unroll
            for (int i = 0; i < 8; i++) rv[i] = rp[i];

            u64 aq0 = 0ull, aq1 = 0ull, ak0 = 0ull, ak1 = 0ull;
#pragma unroll
            for (int i = 0; i < 8; i++) {
                aq0 = ffma2(rv[i].x, wq0[2 * i], aq0); aq0 = ffma2(rv[i].y, wq0[2 * i + 1], aq0);
                aq1 = ffma2(rv[i].x, wq1[2 * i], aq1); aq1 = ffma2(rv[i].y, wq1[2 * i + 1], aq1);
                ak0 = ffma2(rv[i].x, wk0[2 * i], ak0); ak0 = ffma2(rv[i].y, wk0[2 * i + 1], ak0);
                ak1 = ffma2(rv[i].x, wk1[2 * i], ak1); ak1 = ffma2(rv[i].y, wk1[2 * i + 1], ak1);
            }
            float2 t2;
            t2 = unpack2(aq0); float q0 = t2.x + t2.y;
            t2 = unpack2(aq1); float q1 = t2.x + t2.y;
            t2 = unpack2(ak0); float k0 = t2.x + t2.y;
            t2 = unpack2(ak1); float k1 = t2.x + t2.y;
#pragma unroll
            for (int off = 16; off > 0; off >>= 1) {
                q0 += __shfl_xor_sync(0xffffffffu, q0, off);
                q1 += __shfl_xor_sync(0xffffffffu, q1, off);
                k0 += __shfl_xor_sync(0xffffffffu, k0, off);
                k1 += __shfl_xor_sync(0xffffffffu, k1, off);
            }
            int s = s0 + r;
            float m = __ldg(mask + (size_t)b * SS + s);
            if (l == 0) {
                *(float2*)(qs_buf + ((size_t)(b * SS + s)) * HH + h0) =
                    make_float2(q0 * m, q1 * m);
                ks_sh[r * 8 + w] = make_float2(k0 * m, k1 * m);
                if (w == 0) msk_sh[r] = m;
            }
        }
    }
    __syncthreads();

    // -------------------- PASS 2: g + hbar accumulation --------------------
    {
        u64 g0[16], g1[16];
#pragma unroll
        for (int i = 0; i < 16; i++) { g0[i] = 0ull; g1[i] = 0ull; }
        u64 hb0 = 0ull, hb1 = 0ull;   // hbar chunk: e = w*128 + l*4 .. +3

#pragma unroll 1
        for (int r = 0; r < ROWS_PER; r++) {
            const float* row = rowbase + (size_t)r * HIDD;
            const ulonglong2* rp = (const ulonglong2*)row + l * 8;
            ulonglong2 rv[8];
#pragma unroll
            for (int i = 0; i < 8; i++) rv[i] = rp[i];

            float2 ks = ks_sh[r * 8 + w];
            u64 kk0 = pack2(ks.x, ks.x), kk1 = pack2(ks.y, ks.y);
#pragma unroll
            for (int i = 0; i < 8; i++) {
                g0[2 * i]     = ffma2(rv[i].x, kk0, g0[2 * i]);
                g0[2 * i + 1] = ffma2(rv[i].y, kk0, g0[2 * i + 1]);
                g1[2 * i]     = ffma2(rv[i].x, kk1, g1[2 * i]);
                g1[2 * i + 1] = ffma2(rv[i].y, kk1, g1[2 * i + 1]);
            }
            {
                float m = msk_sh[r];
                const ulonglong2 hv = *((const ulonglong2*)(row + w * 128) + l);
                u64 mm = pack2(m, m);
                hb0 = ffma2(hv.x, mm, hb0);
                hb1 = ffma2(hv.y, mm, hb1);
            }
        }

        // write per-block partials (disjoint -> no atomics)
        float* gp0 = g_scratch + ((size_t)blk * HH + h0) * HIDD + l * 32;
        float* gp1 = g_scratch + ((size_t)blk * HH + h0 + 1) * HIDD + l * 32;
#pragma unroll
        for (int j = 0; j < 8; j++) {
            float2 a = unpack2(g0[2 * j]), bxy = unpack2(g0[2 * j + 1]);
            ((float4*)gp0)[j] = make_float4(a.x, a.y, bxy.x, bxy.y);
            a = unpack2(g1[2 * j]); bxy = unpack2(g1[2 * j + 1]);
            ((float4*)gp1)[j] = make_float4(a.x, a.y, bxy.x, bxy.y);
        }
        float2 a = unpack2(hb0), bxy = unpack2(hb1);
        *(float4*)(hbar_scratch + (size_t)blk * HIDD + w * 128 + l * 4) =
            make_float4(a.x, a.y, bxy.x, bxy.y);
    }
}

// ============================================================
// K2a: reduce hbar partials per batch + invlen. grid 8, block 1024
// ============================================================
__global__ void k2a_hbar(const float* __restrict__ mask) {
    int b = blockIdx.x;
    int e = threadIdx.x;
    float a0 = 0.f, a1 = 0.f, a2 = 0.f, a3 = 0.f;
    const float* base = hbar_scratch + (size_t)b * K1_CHUNKS * HIDD + e;
#pragma unroll 4
    for (int c = 0; c < K1_CHUNKS; c += 4) {
        a0 += base[(size_t)(c + 0) * HIDD];
        a1 += base[(size_t)(c + 1) * HIDD];
        a2 += base[(size_t)(c + 2) * HIDD];
        a3 += base[(size_t)(c + 3) * HIDD];
    }
    hbar_final[b * HIDD + e] = (a0 + a1) + (a2 + a3);

    __shared__ float red[1024];
    float a = 0.f;
    for (int i = threadIdx.x; i < SS; i += 1024) a += mask[(size_t)b * SS + i];
    red[threadIdx.x] = a;
    __syncthreads();
    for (int st = 512; st > 0; st >>= 1) {
        if (threadIdx.x < st) red[threadIdx.x] += red[threadIdx.x + st];
        __syncthreads();
    }
    if (threadIdx.x == 0) invlen_buf[b] = 1.f / red[0];
}

// ============================================================
// K2: per (b,h): reduce g partials, then kv/mv = (g|hbar) . Wv rows
// grid 128 (b*16+h), block 1024 (32 warps x 2 d-outputs each)
// ============================================================
__global__ void __launch_bounds__(1024)
k2_kvmv(const float* __restrict__ Wv) {
    int b = blockIdx.x >> 4, h = blockIdx.x & 15;
    __shared__ float gsum[HIDD];
    __shared__ float hsum[HIDD];

    int e = threadIdx.x;
    {
        float a0 = 0.f, a1 = 0.f, a2 = 0.f, a3 = 0.f;
        const float* base = g_scratch + (((size_t)b * K1_CHUNKS) * HH + h) * HIDD + e;
#pragma unroll 4
        for (int c = 0; c < K1_CHUNKS; c += 4) {
            a0 += base[(size_t)(c + 0) * HH * HIDD];
            a1 += base[(size_t)(c + 1) * HH * HIDD];
            a2 += base[(size_t)(c + 2) * HH * HIDD];
            a3 += base[(size_t)(c + 3) * HH * HIDD];
        }
        gsum[e] = (a0 + a1) + (a2 + a3);
        hsum[e] = hbar_final[b * HIDD + e];
    }
    __syncthreads();

    int w = threadIdx.x >> 5, l = threadIdx.x & 31;
#pragma unroll
    for (int dd = 0; dd < 2; dd++) {
        int d = w * 2 + dd;
        const float* wvrow = Wv + (size_t)(h * DHH + d) * HIDD;
        float ak = 0.f, am = 0.f;
#pragma unroll 8
        for (int e2 = l; e2 < HIDD; e2 += 32) {
            float wv = __ldg(wvrow + e2);
            ak += gsum[e2] * wv;
            am += hsum[e2] * wv;
        }
#pragma unroll
        for (int off = 16; off > 0; off >>= 1) {
            ak += __shfl_xor_sync(0xffffffffu, ak, off);
            am += __shfl_xor_sync(0xffffffffu, am, off);
        }
        if (l == 0) {
            kv_buf[((b * HH + h) << 6) + d] = ak;
            mv_buf[((b * HH + h) << 6) + d] = am;
        }
    }
}

// ============================================================
// K3: out[b][s][h*64+d] = (qs[b,s,h]*mv[b,h,d] + kv[b,h,d]) * invlen[b]
// grid 8192 (4 rows each), block 256 (float4 per thread per row)
// ============================================================
__global__ void k3_out(float* __restrict__ out) {
    int row0 = blockIdx.x << 2;    // b*4096 + s, 4 rows per block
    int b = row0 >> 12;
    int t = threadIdx.x;
    int h = t >> 4;
    int d = (t & 15) << 2;
    float4 mv4 = *(const float4*)(mv_buf + ((b * HH + h) << 6) + d);
    float4 kv4 = *(const float4*)(kv_buf + ((b * HH + h) << 6) + d);
    float il = invlen_buf[b];
    float4 mvi = make_float4(mv4.x * il, mv4.y * il, mv4.z * il, mv4.w * il);
    float4 kvi = make_float4(kv4.x * il, kv4.y * il, kv4.z * il, kv4.w * il);
#pragma unroll
    for (int rr = 0; rr < 4; rr++) {
        int row = row0 + rr;
        float qsv = __ldg(qs_buf + (size_t)row * HH + h);
        float4 o;
        o.x = qsv * mvi.x + kvi.x;
        o.y = qsv * mvi.y + kvi.y;
        o.z = qsv * mvi.z + kvi.z;
        o.w = qsv * mvi.w + kvi.w;
        ((float4*)out)[(size_t)row * 256 + t] = o;
    }
}

// ============================================================
extern "C" void kernel_launch(void* const* d_in, const int* in_sizes, int n_in,
                              void* d_out, int out_size) {
    const float* hidden = (const float*)d_in[0];
    const float* mask   = (const float*)d_in[1];
    const float* Wq     = (const float*)d_in[2];
    const float* Wk     = (const float*)d_in[3];
    const float* Wv     = (const float*)d_in[4];
    const float* aw     = (const float*)d_in[5];
    float* out = (float*)d_out;

    k0_weff<<<32, 256>>>(Wq, Wk, aw);
    k1_main<<<K1_BLOCKS, 256>>>(hidden, mask);
    k2a_hbar<<<BB, 1024>>>(mask);
    k2_kvmv<<<BB * HH, 1024>>>(Wv);
    k3_out<<<BB * SS / 4, 256>>>(out);
}

// round 3
// speedup vs baseline: 3.5714x; 3.5714x over previous
#include <cuda_runtime.h>
#include <cstdint>

#define BB   8
#define SS   4096
#define HIDD 1024
#define HH   16
#define DHH  64

#define MT        128                 // rows per k1 block
#define KC        32                  // k-chunk
#define K1_CHUNKS 32                  // chunks per batch (SS/MT)
#define K1_BLOCKS (BB * K1_CHUNKS)    // 256

// ---------- static scratch (no allocations allowed) ----------
__device__ float g_scratch[(size_t)K1_BLOCKS * HH * HIDD]; // 16.8 MB
__device__ float hbar_scratch[(size_t)K1_BLOCKS * HIDD];   // 1 MB
__device__ float wqk_eff[2 * HH * HIDD];                   // 128 KB [vec][e], vec<16: q, vec>=16: k
__device__ float qs_buf[(size_t)BB * SS * HH];             // 2 MB
__device__ float hbar_final[BB * HIDD];
__device__ float kv_buf[BB * HH * DHH];
__device__ float mv_buf[BB * HH * DHH];
__device__ float invlen_buf[BB];

typedef unsigned long long u64;

__device__ __forceinline__ u64 ffma2(u64 a, u64 b, u64 c) {
    u64 d;
    asm("fma.rn.f32x2 %0, %1, %2, %3;" : "=l"(d) : "l"(a), "l"(b), "l"(c));
    return d;
}
__device__ __forceinline__ u64 pack2(float x, float y) {
    u64 r; asm("mov.b64 %0, {%1,%2};" : "=l"(r) : "f"(x), "f"(y)); return r;
}
__device__ __forceinline__ float2 unpack2(u64 v) {
    float2 r; asm("mov.b64 {%0,%1}, %2;" : "=f"(r.x), "=f"(r.y) : "l"(v)); return r;
}

// ============================================================
// K0: wqk_eff[ch*16+h][e] = sum_d aw[h][d] * W[(h*64+d)][e]
// ============================================================
__global__ void k0_weff(const float* __restrict__ Wq,
                        const float* __restrict__ Wk,
                        const float* __restrict__ aw) {
    int ch = blockIdx.x >> 4, h = blockIdx.x & 15;
    const float* W = ch ? Wk : Wq;
    __shared__ float a_sh[DHH];
    if (threadIdx.x < DHH) a_sh[threadIdx.x] = aw[h * DHH + threadIdx.x];
    __syncthreads();
    for (int e = threadIdx.x; e < HIDD; e += blockDim.x) {
        float acc = 0.f;
#pragma unroll 8
        for (int d = 0; d < DHH; d++)
            acc += a_sh[d] * W[(size_t)(h * DHH + d) * HIDD + e];
        wqk_eff[(ch * HH + h) * HIDD + e] = acc;
    }
}

// ============================================================
// K1: per block: 128-row tile.
// Phase A: tiled GEMM C[128x32] = hidden_tile[128x1024] x wqk_eff^T[1024x32]
//          (cols 0..15 = q_scores, 16..31 = k_scores), mask applied,
//          qs -> global, ks -> smem (duplicated-packed for f32x2).
// Phase B: g[h][e] += ks[s][h]*hidden[s][e], hbar[e] += m[s]*hidden[s][e]
//          per-block partials to scratch.
// 256 threads, thread tile 4 rows x 4 cols, occ 2 blocks/SM.
// ============================================================
__global__ void __launch_bounds__(256, 2)
k1_main(const float* __restrict__ hidden, const float* __restrict__ mask) {
    __shared__ float As[MT][KC + 4];     // +4 pad: 16B-aligned, conflict-light
    __shared__ float Bs[KC][32];         // [k][vec]
    __shared__ u64   ks_dup[MT][16];     // (ks,ks) packed per head
    __shared__ u64   m_dup[MT];
    __shared__ float m_sh[MT];

    const int tile = blockIdx.x;
    const int b = tile >> 5;
    const int s0 = (tile & 31) * MT;
    const int tid = threadIdx.x;
    const int tx = tid & 7;              // col-group (4 cols each)
    const int ty = tid >> 3;             // row-group (4 rows each)

    const float* Abase = hidden + ((size_t)b * SS + s0) * HIDD;

    if (tid < MT) {
        float m = mask[(size_t)b * SS + s0 + tid];
        m_sh[tid] = m;
        m_dup[tid] = pack2(m, m);
    }

    u64 acc[4][2];
#pragma unroll
    for (int i = 0; i < 4; i++) { acc[i][0] = 0ull; acc[i][1] = 0ull; }

    float4 aR[4];
    float4 bR;

    // ---- prologue: load chunk 0 ----
#pragma unroll
    for (int i = 0; i < 4; i++) {
        int idx = tid + i * 256;
        int r = idx >> 3, kq = idx & 7;
        aR[i] = *(const float4*)(Abase + (size_t)r * HIDD + kq * 4);
    }
    {
        int v = tid & 31, kq8 = tid >> 5;
        bR = *(const float4*)(wqk_eff + (size_t)v * HIDD + kq8 * 4);
    }
#pragma unroll
    for (int i = 0; i < 4; i++) {
        int idx = tid + i * 256;
        int r = idx >> 3, kq = idx & 7;
        *(float4*)&As[r][kq * 4] = aR[i];
    }
    {
        int v = tid & 31, kq8 = tid >> 5;
        Bs[kq8 * 4 + 0][v] = bR.x;
        Bs[kq8 * 4 + 1][v] = bR.y;
        Bs[kq8 * 4 + 2][v] = bR.z;
        Bs[kq8 * 4 + 3][v] = bR.w;
    }
    __syncthreads();

    // ---- main loop over 32 k-chunks ----
#pragma unroll 1
    for (int c = 0; c < HIDD / KC; c++) {
        if (c + 1 < HIDD / KC) {
            int k0 = (c + 1) * KC;
#pragma unroll
            for (int i = 0; i < 4; i++) {
                int idx = tid + i * 256;
                int r = idx >> 3, kq = idx & 7;
                aR[i] = *(const float4*)(Abase + (size_t)r * HIDD + k0 + kq * 4);
            }
            int v = tid & 31, kq8 = tid >> 5;
            bR = *(const float4*)(wqk_eff + (size_t)v * HIDD + k0 + kq8 * 4);
        }
#pragma unroll
        for (int k = 0; k < KC; k++) {
            u64 b01 = *(const u64*)&Bs[k][tx * 4];
            u64 b23 = *(const u64*)&Bs[k][tx * 4 + 2];
            float a0 = As[ty * 4 + 0][k];
            float a1 = As[ty * 4 + 1][k];
            float a2 = As[ty * 4 + 2][k];
            float a3 = As[ty * 4 + 3][k];
            u64 A0 = pack2(a0, a0), A1 = pack2(a1, a1);
            u64 A2 = pack2(a2, a2), A3 = pack2(a3, a3);
            acc[0][0] = ffma2(A0, b01, acc[0][0]); acc[0][1] = ffma2(A0, b23, acc[0][1]);
            acc[1][0] = ffma2(A1, b01, acc[1][0]); acc[1][1] = ffma2(A1, b23, acc[1][1]);
            acc[2][0] = ffma2(A2, b01, acc[2][0]); acc[2][1] = ffma2(A2, b23, acc[2][1]);
            acc[3][0] = ffma2(A3, b01, acc[3][0]); acc[3][1] = ffma2(A3, b23, acc[3][1]);
        }
        __syncthreads();
        if (c + 1 < HIDD / KC) {
#pragma unroll
            for (int i = 0; i < 4; i++) {
                int idx = tid + i * 256;
                int r = idx >> 3, kq = idx & 7;
                *(float4*)&As[r][kq * 4] = aR[i];
            }
            int v = tid & 31, kq8 = tid >> 5;
            Bs[kq8 * 4 + 0][v] = bR.x;
            Bs[kq8 * 4 + 1][v] = bR.y;
            Bs[kq8 * 4 + 2][v] = bR.z;
            Bs[kq8 * 4 + 3][v] = bR.w;
            __syncthreads();
        }
    }

    // ---- epilogue A: mask, store qs, stage ks ----
#pragma unroll
    for (int i = 0; i < 4; i++) {
        int r = ty * 4 + i;
        float m = m_sh[r];
        float2 p0 = unpack2(acc[i][0]);
        float2 p1 = unpack2(acc[i][1]);
        if (tx < 4) {
            float4 o = make_float4(p0.x * m, p0.y * m, p1.x * m, p1.y * m);
            *(float4*)(qs_buf + ((size_t)(b * SS + s0 + r)) * HH + tx * 4) = o;
        } else {
            int c0 = (tx - 4) * 4;
            float k0v = p0.x * m, k1v = p0.y * m, k2v = p1.x * m, k3v = p1.y * m;
            ks_dup[r][c0 + 0] = pack2(k0v, k0v);
            ks_dup[r][c0 + 1] = pack2(k1v, k1v);
            ks_dup[r][c0 + 2] = pack2(k2v, k2v);
            ks_dup[r][c0 + 3] = pack2(k3v, k3v);
        }
    }
    __syncthreads();

    // ---- phase B: g + hbar accumulation (thread owns 4 e-cols) ----
    u64 g[16][2];
#pragma unroll
    for (int h = 0; h < 16; h++) { g[h][0] = 0ull; g[h][1] = 0ull; }
    u64 hb0 = 0ull, hb1 = 0ull;

    const char* hrow = (const char*)(Abase + tid * 4);
#pragma unroll 2
    for (int r = 0; r < MT; r++) {
        ulonglong2 hv = *(const ulonglong2*)(hrow + (size_t)r * (HIDD * 4));
        u64 md = m_dup[r];
        hb0 = ffma2(hv.x, md, hb0);
        hb1 = ffma2(hv.y, md, hb1);
#pragma unroll
        for (int hh = 0; hh < 8; hh++) {
            ulonglong2 kp = *(const ulonglong2*)&ks_dup[r][hh * 2];
            g[2 * hh + 0][0] = ffma2(hv.x, kp.x, g[2 * hh + 0][0]);
            g[2 * hh + 0][1] = ffma2(hv.y, kp.x, g[2 * hh + 0][1]);
            g[2 * hh + 1][0] = ffma2(hv.x, kp.y, g[2 * hh + 1][0]);
            g[2 * hh + 1][1] = ffma2(hv.y, kp.y, g[2 * hh + 1][1]);
        }
    }

#pragma unroll
    for (int h = 0; h < 16; h++) {
        float2 x = unpack2(g[h][0]), y = unpack2(g[h][1]);
        *(float4*)(g_scratch + ((size_t)tile * HH + h) * HIDD + tid * 4) =
            make_float4(x.x, x.y, y.x, y.y);
    }
    {
        float2 x = unpack2(hb0), y = unpack2(hb1);
        *(float4*)(hbar_scratch + (size_t)tile * HIDD + tid * 4) =
            make_float4(x.x, x.y, y.x, y.y);
    }
}

// ============================================================
// K2a: reduce hbar partials per batch + invlen. grid 8, block 1024
// ============================================================
__global__ void k2a_hbar(const float* __restrict__ mask) {
    int b = blockIdx.x;
    int e = threadIdx.x;
    float a0 = 0.f, a1 = 0.f, a2 = 0.f, a3 = 0.f;
    const float* base = hbar_scratch + (size_t)b * K1_CHUNKS * HIDD + e;
#pragma unroll
    for (int c = 0; c < K1_CHUNKS; c += 4) {
        a0 += base[(size_t)(c + 0) * HIDD];
        a1 += base[(size_t)(c + 1) * HIDD];
        a2 += base[(size_t)(c + 2) * HIDD];
        a3 += base[(size_t)(c + 3) * HIDD];
    }
    hbar_final[b * HIDD + e] = (a0 + a1) + (a2 + a3);

    __shared__ float red[1024];
    float a = 0.f;
    for (int i = threadIdx.x; i < SS; i += 1024) a += mask[(size_t)b * SS + i];
    red[threadIdx.x] = a;
    __syncthreads();
    for (int st = 512; st > 0; st >>= 1) {
        if (threadIdx.x < st) red[threadIdx.x] += red[threadIdx.x + st];
        __syncthreads();
    }
    if (threadIdx.x == 0) invlen_buf[b] = 1.f / red[0];
}

// ============================================================
// K2: per (b,h): reduce g partials, then kv/mv = (g|hbar) . Wv rows
// grid 128, block 1024
// ============================================================
__global__ void __launch_bounds__(1024)
k2_kvmv(const float* __restrict__ Wv) {
    int b = blockIdx.x >> 4, h = blockIdx.x & 15;
    __shared__ float gsum[HIDD];
    __shared__ float hsum[HIDD];

    int e = threadIdx.x;
    {
        float a0 = 0.f, a1 = 0.f, a2 = 0.f, a3 = 0.f;
        const float* base = g_scratch + (((size_t)b * K1_CHUNKS) * HH + h) * HIDD + e;
#pragma unroll
        for (int c = 0; c < K1_CHUNKS; c += 4) {
            a0 += base[(size_t)(c + 0) * HH * HIDD];
            a1 += base[(size_t)(c + 1) * HH * HIDD];
            a2 += base[(size_t)(c + 2) * HH * HIDD];
            a3 += base[(size_t)(c + 3) * HH * HIDD];
        }
        gsum[e] = (a0 + a1) + (a2 + a3);
        hsum[e] = hbar_final[b * HIDD + e];
    }
    __syncthreads();

    int w = threadIdx.x >> 5, l = threadIdx.x & 31;
#pragma unroll
    for (int dd = 0; dd < 2; dd++) {
        int d = w * 2 + dd;
        const float* wvrow = Wv + (size_t)(h * DHH + d) * HIDD;
        float ak = 0.f, am = 0.f;
#pragma unroll 8
        for (int e2 = l; e2 < HIDD; e2 += 32) {
            float wv = __ldg(wvrow + e2);
            ak += gsum[e2] * wv;
            am += hsum[e2] * wv;
        }
#pragma unroll
        for (int off = 16; off > 0; off >>= 1) {
            ak += __shfl_xor_sync(0xffffffffu, ak, off);
            am += __shfl_xor_sync(0xffffffffu, am, off);
        }
        if (l == 0) {
            kv_buf[((b * HH + h) << 6) + d] = ak;
            mv_buf[((b * HH + h) << 6) + d] = am;
        }
    }
}

// ============================================================
// K3: out[b][s][h*64+d] = (qs[b,s,h]*mv[b,h,d] + kv[b,h,d]) * invlen[b]
// grid 8192 (4 rows each), block 256
// ============================================================
__global__ void k3_out(float* __restrict__ out) {
    int row0 = blockIdx.x << 2;
    int b = row0 >> 12;
    int t = threadIdx.x;
    int h = t >> 4;
    int d = (t & 15) << 2;
    float4 mv4 = *(const float4*)(mv_buf + ((b * HH + h) << 6) + d);
    float4 kv4 = *(const float4*)(kv_buf + ((b * HH + h) << 6) + d);
    float il = invlen_buf[b];
    float4 mvi = make_float4(mv4.x * il, mv4.y * il, mv4.z * il, mv4.w * il);
    float4 kvi = make_float4(kv4.x * il, kv4.y * il, kv4.z * il, kv4.w * il);
#pragma unroll
    for (int rr = 0; rr < 4; rr++) {
        int row = row0 + rr;
        float qsv = __ldg(qs_buf + (size_t)row * HH + h);
        float4 o;
        o.x = qsv * mvi.x + kvi.x;
        o.y = qsv * mvi.y + kvi.y;
        o.z = qsv * mvi.z + kvi.z;
        o.w = qsv * mvi.w + kvi.w;
        ((float4*)out)[(size_t)row * 256 + t] = o;
    }
}

// ============================================================
extern "C" void kernel_launch(void* const* d_in, const int* in_sizes, int n_in,
                              void* d_out, int out_size) {
    const float* hidden = (const float*)d_in[0];
    const float* mask   = (const float*)d_in[1];
    const float* Wq     = (const float*)d_in[2];
    const float* Wk     = (const float*)d_in[3];
    const float* Wv     = (const float*)d_in[4];
    const float* aw     = (const float*)d_in[5];
    float* out = (float*)d_out;

    k0_weff<<<32, 256>>>(Wq, Wk, aw);
    k1_main<<<K1_BLOCKS, 256>>>(hidden, mask);
    k2a_hbar<<<BB, 1024>>>(mask);
    k2_kvmv<<<BB * HH, 1024>>>(Wv);
    k3_out<<<BB * SS / 4, 256>>>(out);
}